// round 17
// baseline (speedup 1.0000x reference)
#include <cuda_runtime.h>
#include <cuda_bf16.h>
#include <cstdint>
#include <math.h>

#define B_   4
#define T_   4096
#define C_   512
#define D_   128
#define BT_  (B_ * T_)

typedef __nv_bfloat16 bf16;

// ---------------------------------------------------------------------------
// Device scratch
// ---------------------------------------------------------------------------
__device__ __align__(16) bf16 g_bTh[D_ * C_], g_bTl[D_ * C_];     // basis^T [128][512]
__device__ __align__(16) bf16 g_xbh[BT_ * D_], g_xbl[BT_ * D_];   // xb [BT][128]
__device__ __align__(16) bf16 g_Gth[D_ * D_], g_Gtl[D_ * D_];     // G^T [128][128]
__device__ __align__(16) bf16 g_qgh[BT_ * D_], g_qgl[BT_ * D_];   // qg [BT][128]
__device__ __align__(16) bf16 g_HBth[C_ * D_], g_HBtl[C_ * D_];   // (H@basis^T)^T [512][128]
__device__ float g_H[D_ * D_];

__device__ __forceinline__ void split2(float v, bf16& h, bf16& l) {
    h = __float2bfloat16_rn(v);
    l = __float2bfloat16_rn(v - __bfloat162float(h));
}

// ---------------------------------------------------------------------------
// MMA / async helpers (legacy mma.sync — tcgen05 rejected: harness targets sm_100)
// ---------------------------------------------------------------------------
__device__ __forceinline__ void ldsm_x4(uint32_t r[4], const bf16* p) {
    uint32_t a = (uint32_t)__cvta_generic_to_shared(p);
    asm volatile("ldmatrix.sync.aligned.m8n8.x4.shared.b16 {%0,%1,%2,%3}, [%4];"
                 : "=r"(r[0]), "=r"(r[1]), "=r"(r[2]), "=r"(r[3]) : "r"(a));
}
__device__ __forceinline__ void ldsm_x2(uint32_t r[2], const bf16* p) {
    uint32_t a = (uint32_t)__cvta_generic_to_shared(p);
    asm volatile("ldmatrix.sync.aligned.m8n8.x2.shared.b16 {%0,%1}, [%2];"
                 : "=r"(r[0]), "=r"(r[1]) : "r"(a));
}
__device__ __forceinline__ void ldsm_x2t(uint32_t r[2], const bf16* p) {
    uint32_t a = (uint32_t)__cvta_generic_to_shared(p);
    asm volatile("ldmatrix.sync.aligned.m8n8.x2.trans.shared.b16 {%0,%1}, [%2];"
                 : "=r"(r[0]), "=r"(r[1]) : "r"(a));
}
__device__ __forceinline__ void mma16816(float c[4], const uint32_t a[4], const uint32_t b[2]) {
    asm volatile("mma.sync.aligned.m16n8k16.row.col.f32.bf16.bf16.f32 "
                 "{%0,%1,%2,%3},{%4,%5,%6,%7},{%8,%9},{%0,%1,%2,%3};"
                 : "+f"(c[0]), "+f"(c[1]), "+f"(c[2]), "+f"(c[3])
                 : "r"(a[0]), "r"(a[1]), "r"(a[2]), "r"(a[3]), "r"(b[0]), "r"(b[1]));
}
__device__ __forceinline__ void cpa16(void* dst, const void* src) {
    uint32_t d = (uint32_t)__cvta_generic_to_shared(dst);
    asm volatile("cp.async.cg.shared.global [%0], [%1], 16;" :: "r"(d), "l"(src));
}
__device__ __forceinline__ void cpa16z(void* dst, const void* src, bool ok) {
    uint32_t d = (uint32_t)__cvta_generic_to_shared(dst);
    int sz = ok ? 16 : 0;
    asm volatile("cp.async.cg.shared.global [%0], [%1], 16, %2;"
                 :: "r"(d), "l"(src), "r"(sz));
}
__device__ __forceinline__ void cpa_commit() { asm volatile("cp.async.commit_group;"); }
__device__ __forceinline__ void cpa_wait0()  { asm volatile("cp.async.wait_group 0;"); }

// ---------------------------------------------------------------------------
// prep kernel, 256 threads:
//   blocks 0..15   : gram 16-row slabs (b>>3: 0=G, 1=H; (b&7)*16 = i-slab)
//   blocks 16..271 : basisT split (2 c-rows per block)
// ---------------------------------------------------------------------------
__global__ __launch_bounds__(256) void prep_kernel(const float* __restrict__ basis,
                                                   const float* __restrict__ qc,
                                                   const float* __restrict__ kc,
                                                   const float* __restrict__ vc,
                                                   const float* __restrict__ oc) {
    __shared__ float As[C_][16];    // 32KB A-slab [c][i-local]
    if (blockIdx.x < 16) {
        const int tid = threadIdx.x;
        const int j = tid & 127, ig = tid >> 7;       // ig in {0,1}
        const int y = blockIdx.x >> 3;
        const int ib = (blockIdx.x & 7) * 16;
        const float* A  = y ? vc : qc;
        const float* Bm = y ? oc : kc;

        for (int idx = tid; idx < C_ * 16; idx += 256) {
            const int c = idx >> 4, t = idx & 15;
            As[c][t] = A[c * D_ + ib + t];
        }
        __syncthreads();

        float acc[8];
#pragma unroll
        for (int ii = 0; ii < 8; ii++) acc[ii] = 0.f;

#pragma unroll 8
        for (int c = 0; c < C_; c++) {
            const float bv = Bm[c * D_ + j];
#pragma unroll
            for (int ii = 0; ii < 8; ii++)
                acc[ii] += As[c][ig * 8 + ii] * bv;
        }

#pragma unroll
        for (int ii = 0; ii < 8; ii++) {
            const int i = ib + ig * 8 + ii;
            if (y) {
                g_H[i * D_ + j] = acc[ii];
            } else {
                bf16 h, l; split2(acc[ii], h, l);
                g_Gth[j * D_ + i] = h;
                g_Gtl[j * D_ + i] = l;
            }
        }
    } else {
        const int c = (blockIdx.x - 16) * 2 + (threadIdx.x >> 7);  // 0..511
        const int d = threadIdx.x & 127;
        bf16 h, l;
        split2(basis[c * D_ + d], h, l);
        g_bTh[d * C_ + c] = h;
        g_bTl[d * C_ + c] = l;
    }
}

// ---------------------------------------------------------------------------
// hb body (runs as extra blocks of xbqg kernel)
// ---------------------------------------------------------------------------
struct HbSmem {
    float Hs[D_][D_];
    float bs[32][D_ + 1];
};
__device__ void hb_body(char* raw, const float* __restrict__ basis, int blk) {
    HbSmem* sm = (HbSmem*)raw;
    const int tid = threadIdx.x;
    const int c0 = blk * 32;

    for (int idx = tid; idx < D_ * D_; idx += 256)
        sm->Hs[idx >> 7][idx & 127] = g_H[idx];
    for (int idx = tid; idx < 32 * D_; idx += 256)
        sm->bs[idx >> 7][idx & 127] = basis[(size_t)(c0 + (idx >> 7)) * D_ + (idx & 127)];
    __syncthreads();

    const int cl = tid & 31;
    const int fg = tid >> 5;
    float acc[16];
#pragma unroll
    for (int ff = 0; ff < 16; ff++) acc[ff] = 0.f;

#pragma unroll 4
    for (int e = 0; e < D_; e++) {
        const float bv = sm->bs[cl][e];
#pragma unroll
        for (int ff = 0; ff < 16; ff++)
            acc[ff] += bv * sm->Hs[fg * 16 + ff][e];
    }

    const int c = c0 + cl;
#pragma unroll
    for (int ff = 0; ff < 16; ff += 2) {
        __nv_bfloat162 th, tl;
        split2(acc[ff],     th.x, tl.x);
        split2(acc[ff + 1], th.y, tl.y);
        *(__nv_bfloat162*)&g_HBth[c * D_ + fg * 16 + ff] = th;
        *(__nv_bfloat162*)&g_HBtl[c * D_ + fg * 16 + ff] = tl;
    }
}

// ---------------------------------------------------------------------------
// Fused xb + qg kernel (M-tile 64) + hb blocks. grid 256+16, 256 threads.
// ---------------------------------------------------------------------------
#define GSTR 40
typedef bf16 AStage[64][GSTR];
typedef bf16 BStage[128][GSTR];
typedef bf16 EpRowA[136];
typedef bf16 EpRowB[136];

#define XB_SMEM 104448

__global__ __launch_bounds__(256, 2) void xbqg_kernel(const float* __restrict__ x,
                                                      const float* __restrict__ basis) {
    extern __shared__ char raw[];
    if (blockIdx.x >= BT_ / 64) { hb_body(raw, basis, blockIdx.x - BT_ / 64); return; }

    AStage* Ah = (AStage*)(raw);
    AStage* Al = (AStage*)(raw + 10240);
    BStage* Bh = (BStage*)(raw + 20480);
    BStage* Bl = (BStage*)(raw + 40960);
    EpRowA* Xh = (EpRowA*)(raw);
    EpRowA* Xl = (EpRowA*)(raw + 17408);
    EpRowB* Gh = (EpRowB*)(raw + 34816);
    EpRowB* Gl = (EpRowB*)(raw + 69632);

    const int tid = threadIdx.x, lane = tid & 31, warp = tid >> 5;
    const int wm = warp & 1, wn = warp >> 1;
    const int m0 = blockIdx.x * 64;
    const int ar = tid >> 2, ak = (tid & 3) * 8;
    const int br = tid >> 1, bk = (tid & 1) * 16;
    const int NIT = C_ / 32;

    float acc[2][4][4];
#pragma unroll
    for (int i = 0; i < 2; i++)
#pragma unroll
        for (int j = 0; j < 4; j++)
#pragma unroll
            for (int q = 0; q < 4; q++) acc[i][j][q] = 0.f;

    float4 pf[2];
    {
        const float* p = x + (size_t)(m0 + ar) * C_ + ak;
        float4 a0 = *(const float4*)(p), a1 = *(const float4*)(p + 4);
        bf16 hh[8], ll[8];
        float vs[8] = {a0.x,a0.y,a0.z,a0.w, a1.x,a1.y,a1.z,a1.w};
#pragma unroll
        for (int q = 0; q < 8; q++) split2(vs[q], hh[q], ll[q]);
        *(float4*)&Ah[0][ar][ak] = *(float4*)hh;
        *(float4*)&Al[0][ar][ak] = *(float4*)ll;
        cpa16(&Bh[0][br][bk],     &g_bTh[(size_t)br * C_ + bk]);
        cpa16(&Bh[0][br][bk + 8], &g_bTh[(size_t)br * C_ + bk + 8]);
        cpa16(&Bl[0][br][bk],     &g_bTl[(size_t)br * C_ + bk]);
        cpa16(&Bl[0][br][bk + 8], &g_bTl[(size_t)br * C_ + bk + 8]);
        cpa_commit();
        const float* p1 = x + (size_t)(m0 + ar) * C_ + 32 + ak;
        pf[0] = *(const float4*)(p1);
        pf[1] = *(const float4*)(p1 + 4);
    }

    for (int it = 0; it < NIT; it++) {
        const int buf = it & 1;
        cpa_wait0();
        __syncthreads();
        if (it + 1 < NIT) {
            const int nb = buf ^ 1;
            const int k1 = (it + 1) * 32;
            bf16 hh[8], ll[8];
            float vs[8] = {pf[0].x,pf[0].y,pf[0].z,pf[0].w,
                           pf[1].x,pf[1].y,pf[1].z,pf[1].w};
#pragma unroll
            for (int q = 0; q < 8; q++) split2(vs[q], hh[q], ll[q]);
            *(float4*)&Ah[nb][ar][ak] = *(float4*)hh;
            *(float4*)&Al[nb][ar][ak] = *(float4*)ll;
            cpa16(&Bh[nb][br][bk],     &g_bTh[(size_t)br * C_ + k1 + bk]);
            cpa16(&Bh[nb][br][bk + 8], &g_bTh[(size_t)br * C_ + k1 + bk + 8]);
            cpa16(&Bl[nb][br][bk],     &g_bTl[(size_t)br * C_ + k1 + bk]);
            cpa16(&Bl[nb][br][bk + 8], &g_bTl[(size_t)br * C_ + k1 + bk + 8]);
            cpa_commit();
            if (it + 2 < NIT) {
                const float* p2 = x + (size_t)(m0 + ar) * C_ + (it + 2) * 32 + ak;
                pf[0] = *(const float4*)(p2);
                pf[1] = *(const float4*)(p2 + 4);
            }
        }

#pragma unroll
        for (int ks = 0; ks < 2; ks++) {
            uint32_t ah[2][4], al[2][4], bh[4][2], bl[4][2];
#pragma unroll
            for (int mt = 0; mt < 2; mt++) {
                const int rr = wm * 32 + mt * 16 + (lane & 15);
                const int kk = ks * 16 + (lane >> 4) * 8;
                ldsm_x4(ah[mt], &Ah[buf][rr][kk]);
                ldsm_x4(al[mt], &Al[buf][rr][kk]);
            }
#pragma unroll
            for (int nt = 0; nt < 4; nt++) {
                const int rr = wn * 32 + nt * 8 + (lane & 7);
                const int kk = ks * 16 + ((lane >> 3) & 1) * 8;
                ldsm_x2(bh[nt], &Bh[buf][rr][kk]);
                ldsm_x2(bl[nt], &Bl[buf][rr][kk]);
            }
#pragma unroll
            for (int mt = 0; mt < 2; mt++)
#pragma unroll
                for (int nt = 0; nt < 4; nt++)
                    mma16816(acc[mt][nt], ah[mt], bh[nt]);
#pragma unroll
            for (int mt = 0; mt < 2; mt++)
#pragma unroll
                for (int nt = 0; nt < 4; nt++)
                    mma16816(acc[mt][nt], ah[mt], bl[nt]);
#pragma unroll
            for (int mt = 0; mt < 2; mt++)
#pragma unroll
                for (int nt = 0; nt < 4; nt++)
                    mma16816(acc[mt][nt], al[mt], bh[nt]);
        }
    }
    __syncthreads();

#pragma unroll
    for (int p = 0; p < 8; p++) {
        const int idx = p * 256 + tid;
        const int row = idx >> 4;
        const int seg = (idx & 15) * 8;
        cpa16(&Gh[row][seg], &g_Gth[row * D_ + seg]);
        cpa16(&Gl[row][seg], &g_Gtl[row * D_ + seg]);
    }
    cpa_commit();

#pragma unroll
    for (int mt = 0; mt < 2; mt++)
#pragma unroll
        for (int nt = 0; nt < 4; nt++) {
            const int rl0 = wm * 32 + mt * 16 + (lane >> 2);
            const int cc  = wn * 32 + nt * 8 + (lane & 3) * 2;
#pragma unroll
            for (int h = 0; h < 2; h++) {
                const int rr = rl0 + h * 8;
                __nv_bfloat162 th, tl;
                split2(acc[mt][nt][h * 2 + 0], th.x, tl.x);
                split2(acc[mt][nt][h * 2 + 1], th.y, tl.y);
                *(__nv_bfloat162*)&g_xbh[(size_t)(m0 + rr) * D_ + cc] = th;
                *(__nv_bfloat162*)&g_xbl[(size_t)(m0 + rr) * D_ + cc] = tl;
                *(__nv_bfloat162*)&Xh[rr][cc] = th;
                *(__nv_bfloat162*)&Xl[rr][cc] = tl;
            }
        }
    cpa_wait0();
    __syncthreads();

    float acc2[2][4][4];
#pragma unroll
    for (int i = 0; i < 2; i++)
#pragma unroll
        for (int j = 0; j < 4; j++)
#pragma unroll
            for (int q = 0; q < 4; q++) acc2[i][j][q] = 0.f;

#pragma unroll
    for (int ks = 0; ks < 8; ks++) {
        uint32_t ah[2][4], al[2][4], bh[4][2], bl[4][2];
#pragma unroll
        for (int mt = 0; mt < 2; mt++) {
            const int rr = wm * 32 + mt * 16 + (lane & 15);
            const int kk = ks * 16 + (lane >> 4) * 8;
            ldsm_x4(ah[mt], &Xh[rr][kk]);
            ldsm_x4(al[mt], &Xl[rr][kk]);
        }
#pragma unroll
        for (int nt = 0; nt < 4; nt++) {
            const int rr = wn * 32 + nt * 8 + (lane & 7);
            const int kk = ks * 16 + ((lane >> 3) & 1) * 8;
            ldsm_x2(bh[nt], &Gh[rr][kk]);
            ldsm_x2(bl[nt], &Gl[rr][kk]);
        }
#pragma unroll
        for (int mt = 0; mt < 2; mt++)
#pragma unroll
            for (int nt = 0; nt < 4; nt++)
                mma16816(acc2[mt][nt], ah[mt], bh[nt]);
#pragma unroll
        for (int mt = 0; mt < 2; mt++)
#pragma unroll
            for (int nt = 0; nt < 4; nt++)
                mma16816(acc2[mt][nt], ah[mt], bl[nt]);
#pragma unroll
        for (int mt = 0; mt < 2; mt++)
#pragma unroll
            for (int nt = 0; nt < 4; nt++)
                mma16816(acc2[mt][nt], al[mt], bh[nt]);
    }

#pragma unroll
    for (int mt = 0; mt < 2; mt++)
#pragma unroll
        for (int nt = 0; nt < 4; nt++) {
            const int rl0 = wm * 32 + mt * 16 + (lane >> 2);
            const int cc  = wn * 32 + nt * 8 + (lane & 3) * 2;
#pragma unroll
            for (int h = 0; h < 2; h++) {
                const int rr = rl0 + h * 8;
                __nv_bfloat162 th, tl;
                split2(acc2[mt][nt][h * 2 + 0], th.x, tl.x);
                split2(acc2[mt][nt][h * 2 + 1], th.y, tl.y);
                *(__nv_bfloat162*)&g_qgh[(size_t)(m0 + rr) * D_ + cc] = th;
                *(__nv_bfloat162*)&g_qgl[(size_t)(m0 + rr) * D_ + cc] = tl;
            }
        }
}

// ---------------------------------------------------------------------------
// Fused attention + output GEMM. NT=5 window, then out = (r @ HB) * scale.
// ---------------------------------------------------------------------------
#define AT_NT 5
#define AT_WT 512

struct AttnSmem {
    bf16 qh[128][136], ql[128][136];     // 69632 ; out phase: Rh/Rl
    bf16 kh[2][64][136], kl[2][64][136]; // 69632 ; out phase: HB chunk bufs
    bf16 sh[128][72],  sl[128][72];      // 36864
    float wtbl[AT_WT];                   // 2048
};

__global__ __launch_bounds__(256, 1) void attn_out_kernel(const float* __restrict__ dlp,
                                                          float* __restrict__ out,
                                                          const float* __restrict__ scale_p) {
    extern __shared__ char raw[];
    AttnSmem* sm = (AttnSmem*)raw;
    const int tid = threadIdx.x, lane = tid & 31, warp = tid >> 5;
    const int wm = warp & 1, wn = warp >> 1;
    const int b = blockIdx.y;
    const int i0 = blockIdx.x * 128;
    const size_t base = (size_t)b * T_ * D_;

    {
        const float dl = *dlp;
        const float decay = 1.0f / (1.0f + expf(-dl));
        const float l2d = log2f(decay);
        for (int e = tid; e < AT_WT; e += 256)
            sm->wtbl[e] = exp2f((float)e * l2d);
    }

#pragma unroll
    for (int p = 0; p < 8; p++) {
        const int idx = p * 256 + tid;
        const int row = idx >> 4;
        const int c8 = (idx & 15) * 8;
        cpa16(&sm->qh[row][c8], &g_qgh[base + (size_t)(i0 + row) * D_ + c8]);
        cpa16(&sm->ql[row][c8], &g_qgl[base + (size_t)(i0 + row) * D_ + c8]);
    }
#pragma unroll
    for (int p = 0; p < 4; p++) {
        const int idx = p * 256 + tid;
        const int row = idx >> 4;
        const int c8 = (idx & 15) * 8;
        const int s = i0 + row;
        const int sc = s < T_ ? s : 0;
        cpa16z(&sm->kh[0][row][c8], &g_xbh[base + (size_t)sc * D_ + c8], s < T_);
        cpa16z(&sm->kl[0][row][c8], &g_xbl[base + (size_t)sc * D_ + c8], s < T_);
    }
    cpa_commit();

    float racc[4][4][4];
#pragma unroll
    for (int i = 0; i < 4; i++)
#pragma unroll
        for (int j = 0; j < 4; j++)
#pragma unroll
            for (int q = 0; q < 4; q++) racc[i][j][q] = 0.f;

    for (int tt = 0; tt < AT_NT; tt++) {
        const int buf = tt & 1;
        const int s0 = i0 + tt * 64;
        cpa_wait0();
        __syncthreads();

        if (tt + 1 < AT_NT) {
            const int nb = buf ^ 1;
            const int s0n = i0 + (tt + 1) * 64;
#pragma unroll
            for (int p = 0; p < 4; p++) {
                const int idx = p * 256 + tid;
                const int row = idx >> 4;
                const int c8 = (idx & 15) * 8;
                const int s = s0n + row;
                const int sc = s < T_ ? s : 0;
                cpa16z(&sm->kh[nb][row][c8], &g_xbh[base + (size_t)sc * D_ + c8], s < T_);
                cpa16z(&sm->kl[nb][row][c8], &g_xbl[base + (size_t)sc * D_ + c8], s < T_);
            }
            cpa_commit();
        }

        float sacc[4][2][4];
#pragma unroll
        for (int i = 0; i < 4; i++)
#pragma unroll
            for (int j = 0; j < 2; j++)
#pragma unroll
                for (int q = 0; q < 4; q++) sacc[i][j][q] = 0.f;

#pragma unroll
        for (int ks = 0; ks < 8; ks++) {
            uint32_t ah[4][4], al[4][4], bh[2][2], bl[2][2];
#pragma unroll
            for (int mt = 0; mt < 4; mt++) {
                const int rr = wm * 64 + mt * 16 + (lane & 15);
                const int kk = ks * 16 + (lane >> 4) * 8;
                ldsm_x4(ah[mt], &sm->qh[rr][kk]);
                ldsm_x4(al[mt], &sm->ql[rr][kk]);
            }
#pragma unroll
            for (int nt = 0; nt < 2; nt++) {
                const int rr = wn * 16 + nt * 8 + (lane & 7);
                const int kk = ks * 16 + ((lane >> 3) & 1) * 8;
                ldsm_x2(bh[nt], &sm->kh[buf][rr][kk]);
                ldsm_x2(bl[nt], &sm->kl[buf][rr][kk]);
            }
#pragma unroll
            for (int mt = 0; mt < 4; mt++)
#pragma unroll
                for (int nt = 0; nt < 2; nt++)
                    mma16816(sacc[mt][nt], ah[mt], bh[nt]);
#pragma unroll
            for (int mt = 0; mt < 4; mt++)
#pragma unroll
                for (int nt = 0; nt < 2; nt++)
                    mma16816(sacc[mt][nt], ah[mt], bl[nt]);
#pragma unroll
            for (int mt = 0; mt < 4; mt++)
#pragma unroll
                for (int nt = 0; nt < 2; nt++)
                    mma16816(sacc[mt][nt], al[mt], bh[nt]);
        }

#pragma unroll
        for (int mt = 0; mt < 4; mt++)
#pragma unroll
            for (int nt = 0; nt < 2; nt++) {
                const int rl0 = wm * 64 + mt * 16 + (lane >> 2);
                const int cc  = wn * 16 + nt * 8 + (lane & 3) * 2;
#pragma unroll
                for (int h = 0; h < 2; h++) {
                    const int rr = rl0 + h * 8;
                    const int e0 = (s0 + cc) - (i0 + rr) - 1;
                    const float w0 = (e0 >= 0) ? sm->wtbl[e0] : 0.f;
                    const float w1 = (e0 + 1 >= 0) ? sm->wtbl[e0 + 1] : 0.f;
                    const float v0 = sacc[mt][nt][h * 2 + 0] * w0;
                    const float v1 = sacc[mt][nt][h * 2 + 1] * w1;
                    __nv_bfloat162 th, tl;
                    split2(v0, th.x, tl.x);
                    split2(v1, th.y, tl.y);
                    *(__nv_bfloat162*)&sm->sh[rr][cc] = th;
                    *(__nv_bfloat162*)&sm->sl[rr][cc] = tl;
                }
            }
        __syncthreads();

#pragma unroll
        for (int ks = 0; ks < 4; ks++) {
            uint32_t ah[4][4], al[4][4], bh[4][2], bl[4][2];
#pragma unroll
            for (int mt = 0; mt < 4; mt++) {
                const int rr = wm * 64 + mt * 16 + (lane & 15);
                const int kk = ks * 16 + (lane >> 4) * 8;
                ldsm_x4(ah[mt], &sm->sh[rr][kk]);
                ldsm_x4(al[mt], &sm->sl[rr][kk]);
            }
            const int srow = ks * 16 + (lane & 7) + ((lane >> 3) & 1) * 8;
#pragma unroll
            for (int nt = 0; nt < 4; nt++) {
                const int ccol = wn * 32 + nt * 8;
                ldsm_x2t(bh[nt], &sm->kh[buf][srow][ccol]);
                ldsm_x2t(bl[nt], &sm->kl[buf][srow][ccol]);
            }
#pragma unroll
            for (int mt = 0; mt < 4; mt++)
#pragma unroll
                for (int nt = 0; nt < 4; nt++)
                    mma16816(racc[mt][nt], ah[mt], bh[nt]);
#pragma unroll
            for (int mt = 0; mt < 4; mt++)
#pragma unroll
                for (int nt = 0; nt < 4; nt++)
                    mma16816(racc[mt][nt], ah[mt], bl[nt]);
#pragma unroll
            for (int mt = 0; mt < 4; mt++)
#pragma unroll
                for (int nt = 0; nt < 4; nt++)
                    mma16816(racc[mt][nt], al[mt], bh[nt]);
        }
    }

    // =======================================================================
    // OUT phase
    // =======================================================================
    __syncthreads();

    bf16 (*Rh)[136] = (bf16(*)[136])sm->qh;
    bf16 (*Rl)[136] = (bf16(*)[136])sm->ql;

    {
        bf16 (*Hh)[136] = (bf16(*)[136])sm->kh[0];
        bf16 (*Hl)[136] = (bf16(*)[136])sm->kh[1];
#pragma unroll
        for (int p = 0; p < 4; p++) {
            const int idx = p * 256 + tid;
            const int row = idx >> 4;
            const int seg = (idx & 15) * 8;
            cpa16(&Hh[row][seg], &g_HBth[(size_t)row * D_ + seg]);
            cpa16(&Hl[row][seg], &g_HBtl[(size_t)row * D_ + seg]);
        }
        cpa_commit();
    }

#pragma unroll
    for (int mt = 0; mt < 4; mt++)
#pragma unroll
        for (int nt = 0; nt < 4; nt++) {
            const int rl0 = wm * 64 + mt * 16 + (lane >> 2);
            const int cc  = wn * 32 + nt * 8 + (lane & 3) * 2;
#pragma unroll
            for (int h = 0; h < 2; h++) {
                const int rr = rl0 + h * 8;
                __nv_bfloat162 th, tl;
                split2(racc[mt][nt][h * 2 + 0], th.x, tl.x);
                split2(racc[mt][nt][h * 2 + 1], th.y, tl.y);
                *(__nv_bfloat162*)&Rh[rr][cc] = th;
                *(__nv_bfloat162*)&Rl[rr][cc] = tl;
            }
        }

    const float s = *scale_p;
    const size_t orow0 = (size_t)b * T_ + i0;

    for (int c = 0; c < 8; c++) {
        const int cb = c & 1;
        bf16 (*Hh)[136] = cb ? (bf16(*)[136])sm->kl[0] : (bf16(*)[136])sm->kh[0];
        bf16 (*Hl)[136] = cb ? (bf16(*)[136])sm->kl[1] : (bf16(*)[136])sm->kh[1];
        cpa_wait0();
        __syncthreads();

        if (c + 1 < 8) {
            const int nb2 = cb ^ 1;
            bf16 (*Nh)[136] = nb2 ? (bf16(*)[136])sm->kl[0] : (bf16(*)[136])sm->kh[0];
            bf16 (*Nl)[136] = nb2 ? (bf16(*)[136])sm->kl[1] : (bf16(*)[136])sm->kh[1];
            const size_t nrow0 = (size_t)(c + 1) * 64;
#pragma unroll
            for (int p = 0; p < 4; p++) {
                const int idx = p * 256 + tid;
                const int row = idx >> 4;
                const int seg = (idx & 15) * 8;
                cpa16(&Nh[row][seg], &g_HBth[(nrow0 + row) * D_ + seg]);
                cpa16(&Nl[row][seg], &g_HBtl[(nrow0 + row) * D_ + seg]);
            }
            cpa_commit();
        }

        float oacc[4][2][4];
#pragma unroll
        for (int i = 0; i < 4; i++)
#pragma unroll
            for (int j = 0; j < 2; j++)
#pragma unroll
                for (int q = 0; q < 4; q++) oacc[i][j][q] = 0.f;

#pragma unroll
        for (int ks = 0; ks < 8; ks++) {
            uint32_t ah[4][4], al[4][4], bh[2][2], bl[2][2];
#pragma unroll
            for (int mt = 0; mt < 4; mt++) {
                const int rr = wm * 64 + mt * 16 + (lane & 15);
                const int kk = ks * 16 + (lane >> 4) * 8;
                ldsm_x4(ah[mt], &Rh[rr][kk]);
                ldsm_x4(al[mt], &Rl[rr][kk]);
            }
#pragma unroll
            for (int nt = 0; nt < 2; nt++) {
                const int rr = wn * 16 + nt * 8 + (lane & 7);
                const int kk = ks * 16 + ((lane >> 3) & 1) * 8;
                ldsm_x2(bh[nt], &Hh[rr][kk]);
                ldsm_x2(bl[nt], &Hl[rr][kk]);
            }
#pragma unroll
            for (int mt = 0; mt < 4; mt++)
#pragma unroll
                for (int nt = 0; nt < 2; nt++)
                    mma16816(oacc[mt][nt], ah[mt], bh[nt]);
#pragma unroll
            for (int mt = 0; mt < 4; mt++)
#pragma unroll
                for (int nt = 0; nt < 2; nt++)
                    mma16816(oacc[mt][nt], ah[mt], bl[nt]);
#pragma unroll
            for (int mt = 0; mt < 4; mt++)
#pragma unroll
                for (int nt = 0; nt < 2; nt++)
                    mma16816(oacc[mt][nt], al[mt], bh[nt]);
        }

#pragma unroll
        for (int mt = 0; mt < 4; mt++)
#pragma unroll
            for (int nt = 0; nt < 2; nt++) {
                const int rl0 = wm * 64 + mt * 16 + (lane >> 2);
                const int cc  = c * 64 + wn * 16 + nt * 8 + (lane & 3) * 2;
#pragma unroll
                for (int h = 0; h < 2; h++) {
                    const int rr = rl0 + h * 8;
                    float2 v = make_float2(oacc[mt][nt][h * 2 + 0] * s,
                                           oacc[mt][nt][h * 2 + 1] * s);
                    *(float2*)&out[(orow0 + rr) * C_ + cc] = v;
                }
            }
    }
}

// ---------------------------------------------------------------------------
// Launch: 3 kernels total
// ---------------------------------------------------------------------------
extern "C" void kernel_launch(void* const* d_in, const int* in_sizes, int n_in,
                              void* d_out, int out_size)
{
    const float* x           = (const float*)d_in[0];
    const float* basis       = (const float*)d_in[1];
    const float* qc          = (const float*)d_in[2];
    const float* kc          = (const float*)d_in[3];
    const float* vc          = (const float*)d_in[4];
    const float* oc          = (const float*)d_in[5];
    const float* decay_logit = (const float*)d_in[6];
    const float* out_scale   = (const float*)d_in[7];
    float* out = (float*)d_out;

    cudaFuncSetAttribute(attn_out_kernel, cudaFuncAttributeMaxDynamicSharedMemorySize,
                         (int)sizeof(AttnSmem));
    cudaFuncSetAttribute(xbqg_kernel, cudaFuncAttributeMaxDynamicSharedMemorySize, XB_SMEM);

    prep_kernel<<<272, 256>>>(basis, qc, kc, vc, oc);
    xbqg_kernel<<<BT_ / 64 + 16, 256, XB_SMEM>>>(x, basis);
    attn_out_kernel<<<dim3(T_ / 128, B_), 256, sizeof(AttnSmem)>>>(decay_logit, out, out_scale);
}